// round 9
// baseline (speedup 1.0000x reference)
#include <cuda_runtime.h>
#include <cuda_bf16.h>
#include <math.h>

#define Hh 64
#define Ff 10
#define Tt 60
#define Dd 6
#define Bb 2048

typedef unsigned long long ull;

// bf16x2 (G0,G1) recurrent weights per warp role w = g*2 + hs:
//   g=0 -> (U_i, U_ste), g=1 -> (U_c, U_o); column h = hs*32 + lane.
// g_Ubf[w][j*32 + lane] = bf16x2( G0[j][h], G1[j][h] )
__device__ unsigned int g_Ubf[4][Hh * 32];

__global__ void prep_kernel(const float* __restrict__ Ui, const float* __restrict__ Us,
                            const float* __restrict__ Uc, const float* __restrict__ Uo) {
    int idx = blockIdx.x * blockDim.x + threadIdx.x;   // [0, 4*64*32)
    if (idx < 4 * Hh * 32) {
        int w = idx >> 11, r = idx & 2047;
        int j = r >> 5, lane = r & 31;
        int g = w >> 1, hs = w & 1;
        int h = hs * 32 + lane;
        const float* G0 = g ? Uc : Ui;
        const float* G1 = g ? Uo : Us;
        __nv_bfloat162 p = __floats2bfloat162_rn(G0[j * Hh + h], G1[j * Hh + h]);
        g_Ubf[w][r] = *reinterpret_cast<unsigned int*>(&p);
    }
}

__device__ __forceinline__ float hsig(float v) {
    return __saturatef(fmaf(v, 0.16666667f, 0.5f));
}
__device__ __forceinline__ ull pack2(float lo, float hi) {
    ull r; asm("mov.b64 %0, {%1, %2};" : "=l"(r) : "f"(lo), "f"(hi)); return r;
}
__device__ __forceinline__ ull fma2(ull a, ull b, ull c) {
    ull d; asm("fma.rn.f32x2 %0, %1, %2, %3;" : "=l"(d) : "l"(a), "l"(b), "l"(c)); return d;
}
__device__ __forceinline__ float2 unpack2(ull v) {
    float lo, hi; asm("mov.b64 {%0, %1}, %2;" : "=f"(lo), "=f"(hi) : "l"(v));
    return make_float2(lo, hi);
}
// bf16x2(G0,G1) -> f32x2 pair (G0,G1): 2 ALU ops.
__device__ __forceinline__ ull bf2f2(unsigned int u) {
    float lo = __uint_as_float(u << 16);
    float hi = __uint_as_float(u & 0xFFFF0000u);
    return pack2(lo, hi);
}
// tanh(x) = 1 - 2/(exp(2x)+1): MUFU.EX2 + MUFU.RCP, abs err ~1e-6
__device__ __forceinline__ float ftanh(float x) {
    float e = __expf(2.0f * x);
    float r;
    asm("rcp.approx.f32 %0, %1;" : "=f"(r) : "f"(e + 1.0f));
    return fmaf(-2.0f, r, 1.0f);
}

// Block = 128 threads = 4 warps sharing 4 batches.
// Warp w: g = w>>1 (gate pair), hs = w&1 (column half). U slice lives in 64 regs.
// Tail + fre: warp w owns batch w; lane covers columns {lane, lane+32}.
__global__ __launch_bounds__(128, 4) void sfm_kernel(
    const float* __restrict__ x,
    const float* __restrict__ W_i,   const float* __restrict__ b_i,
    const float* __restrict__ W_ste, const float* __restrict__ b_ste,
    const float* __restrict__ W_fre, const float* __restrict__ U_fre, const float* __restrict__ b_fre,
    const float* __restrict__ W_c,   const float* __restrict__ b_c,
    const float* __restrict__ W_o,   const float* __restrict__ b_o,
    const float* __restrict__ U_a,   const float* __restrict__ b_a,
    const float* __restrict__ W_p,   const float* __restrict__ b_p,
    float* __restrict__ out)
{
    __shared__ __align__(16) ull   sh_xd[Tt * Dd * 4];   // dup (x,x) pairs, [t][d][b]
    __shared__ __align__(16) ull   sh_hd[Hh][4];         // dup (h,h) pairs, [col][b]
    __shared__ float               sh_hp[Hh][4];         // plain h, [col][b]
    __shared__ __align__(16) ull   sh_ex[4][4][32];      // gate exchange [writer w][b][lane]
    __shared__ __align__(8) float2 sh_cssn[Tt * Ff];
    __shared__ float               sh_UfT[Ff * 65];      // [f][j], padded rows
    __shared__ __align__(16) ull   sh_W[4][32][7];       // [w][lane][d0..5, bias]
    __shared__ float               sh_wfre[Ff][7];       // [f][d0..5, b_fre]
    __shared__ float               sh_ua[Ff];
    __shared__ float               sh_ba[Hh];

    const int tid  = threadIdx.x;
    const int lane = tid & 31;
    const int w    = tid >> 5;
    const int g    = w >> 1;
    const int hs   = w & 1;
    const int h    = hs * 32 + lane;
    const int bbase = blockIdx.x * 4;

    // ---- one-time staging ----
    const float* xg = x + (size_t)bbase * (Tt * Dd);
    for (int i = tid; i < Tt * Dd * 4; i += 128) {
        int b = i & 3, r = i >> 2;               // r = t*6 + d
        float v = xg[b * (Tt * Dd) + r];
        sh_xd[i] = pack2(v, v);
    }
    for (int i = tid; i < Tt * Ff; i += 128) {
        int tt = i / Ff + 1, f = i % Ff;
        int m  = (tt * f) % Ff;
        float ang = (float)m * 0.62831853071795864769f; // 2*pi/10
        float s, c; sincosf(ang, &s, &c);
        sh_cssn[i] = make_float2(c, s);
    }
    for (int i = tid; i < Ff * Hh; i += 128) {
        int f = i >> 6, j = i & 63;
        sh_UfT[f * 65 + j] = U_fre[j * Ff + f];
    }
    for (int i = tid; i < Ff * 7; i += 128) {
        int f = i / 7, k = i % 7;
        sh_wfre[f][k] = (k < 6) ? W_fre[k * Ff + f] : b_fre[f];
    }
    if (tid < Ff) sh_ua[tid] = U_a[tid];
    if (tid < Hh) {
        sh_ba[tid] = b_a[tid];
#pragma unroll
        for (int b = 0; b < 4; b++) { sh_hd[tid][b] = 0ull; sh_hp[tid][b] = 0.0f; }
    }
    {
        const float* G0w = g ? W_c : W_i;
        const float* G1w = g ? W_o : W_ste;
#pragma unroll
        for (int d = 0; d < Dd; d++)
            sh_W[w][lane][d] = pack2(G0w[d * Hh + h], G1w[d * Hh + h]);
        const float* bg0 = g ? b_c : b_i;
        const float* bg1 = g ? b_o : b_ste;
        sh_W[w][lane][6] = pack2(bg0[h], bg1[h]);
    }

    // ---- U slice into registers (64 regs), never re-read ----
    unsigned int ub[Hh];
    {
        const unsigned int* Ubase = &g_Ubf[w][0];
#pragma unroll
        for (int j = 0; j < Hh; j++) ub[j] = Ubase[j * 32 + lane];
    }

    const bool duty = (lane < Ff);   // fre lanes: f = lane, batch = w

    // Oscillator state for batch w, columns {lane, lane+32}.
    float sre[2][Ff], sim[2][Ff];
#pragma unroll
    for (int cc = 0; cc < 2; cc++)
#pragma unroll
        for (int f = 0; f < Ff; f++) { sre[cc][f] = 0.0f; sim[cc][f] = 0.0f; }

    __syncthreads();

    float hl0 = 0.0f, hl1 = 0.0f;   // batch w's h at cols lane / lane+32

    for (int t = 0; t < Tt; t++) {
        // ---- seeds: (g0,g1) bias + x_t @ (Wg0,Wg1) for 4 batches ----
        ull acc0, acc1, acc2, acc3;
        {
            ull bias = sh_W[w][lane][6];
            acc0 = bias; acc1 = bias; acc2 = bias; acc3 = bias;
        }
        float af = 0.0f;
        if (duty) af = sh_wfre[lane][6];
        const ull* xrow = &sh_xd[t * (Dd * 4)];
#pragma unroll
        for (int d = 0; d < Dd; d++) {
            ull Wd = sh_W[w][lane][d];
            ulonglong2 xA = *(const ulonglong2*)&xrow[d * 4];
            ulonglong2 xB = *(const ulonglong2*)&xrow[d * 4 + 2];
            acc0 = fma2(xA.x, Wd, acc0);
            acc1 = fma2(xA.y, Wd, acc1);
            acc2 = fma2(xB.x, Wd, acc2);
            acc3 = fma2(xB.y, Wd, acc3);
            if (duty) {
                float xv = ((const float*)&xrow[d * 4 + w])[0];   // batch w, broadcast
                af = fmaf(xv, sh_wfre[lane][d], af);
            }
        }

        // ---- recurrent matmul: zero LDG; U from regs, h dup pairs from shared ----
#pragma unroll
        for (int j = 0; j < Hh; j++) {
            ulonglong2 hA = *(const ulonglong2*)&sh_hd[j][0];   // (b0b0, b1b1) bcast
            ulonglong2 hB = *(const ulonglong2*)&sh_hd[j][2];   // (b2b2, b3b3)
            ull up = bf2f2(ub[j]);                              // (g0,g1) f32 pair
            acc0 = fma2(hA.x, up, acc0);
            acc1 = fma2(hA.y, up, acc1);
            acc2 = fma2(hB.x, up, acc2);
            acc3 = fma2(hB.y, up, acc3);
            if (duty) af = fmaf(sh_hp[j][w], sh_UfT[lane * 65 + j], af);
        }
        const float frev = hsig(af);   // fre[w][lane] on duty lanes

        // ---- exchange: publish my gate pair for all 4 batches ----
        sh_ex[w][0][lane] = acc0;
        sh_ex[w][1][lane] = acc1;
        sh_ex[w][2][lane] = acc2;
        sh_ex[w][3][lane] = acc3;
        __syncthreads();   // exchange visible; sh_hd/hp reads of this step done

        // Gather all 4 gates for MY batch (w) at both columns.
        float2 is0 = unpack2(sh_ex[0][w][lane]);   // (i,ste) @ col lane
        float2 is1 = unpack2(sh_ex[1][w][lane]);   // (i,ste) @ col lane+32
        float2 co0 = unpack2(sh_ex[2][w][lane]);   // (c,o)   @ col lane
        float2 co1 = unpack2(sh_ex[3][w][lane]);   // (c,o)   @ col lane+32

        // ---- elementwise tail for batch w, 2 columns ----
        float iv0 = hsig(is0.x), sv0 = hsig(is0.y), ov0 = hsig(co0.y);
        float iv1 = hsig(is1.x), sv1 = hsig(is1.y), ov1 = hsig(co1.y);
        float cv0 = iv0 * ftanh(co0.x);
        float cv1 = iv1 * ftanh(co1.x);
        float acca0 = sh_ba[lane];
        float acca1 = sh_ba[lane + 32];
        const float2* crow = &sh_cssn[t * Ff];
#pragma unroll
        for (int f = 0; f < Ff; f++) {
            float frf = __shfl_sync(0xffffffffu, frev, f);
            float2 cn = crow[f];
            float uaf = sh_ua[f];
            float fv0 = sv0 * frf;
            float r0 = fmaf(fv0, sre[0][f], cv0 * cn.x);
            float m0 = fmaf(fv0, sim[0][f], cv0 * cn.y);
            sre[0][f] = r0; sim[0][f] = m0;
            acca0 = fmaf(fmaf(r0, r0, m0 * m0), uaf, acca0);
            float fv1 = sv1 * frf;
            float r1 = fmaf(fv1, sre[1][f], cv1 * cn.x);
            float m1 = fmaf(fv1, sim[1][f], cv1 * cn.y);
            sre[1][f] = r1; sim[1][f] = m1;
            acca1 = fmaf(fmaf(r1, r1, m1 * m1), uaf, acca1);
        }
        hl0 = ov0 * ftanh(acca0);
        hl1 = ov1 * ftanh(acca1);

        // ---- publish batch w's new h at both columns ----
        sh_hd[lane][w]      = pack2(hl0, hl0);
        sh_hd[lane + 32][w] = pack2(hl1, hl1);
        sh_hp[lane][w]      = hl0;
        sh_hp[lane + 32][w] = hl1;
        __syncthreads();   // new h visible for next step
    }

    // ---- projection: out[bbase+w] = h_w @ W_p + b_p (warp butterfly) ----
    {
        float p = fmaf(hl0, W_p[lane], hl1 * W_p[lane + 32]);
#pragma unroll
        for (int off = 16; off >= 1; off >>= 1)
            p += __shfl_xor_sync(0xffffffffu, p, off);
        if (lane == 0) out[bbase + w] = p + b_p[0];
    }
}

extern "C" void kernel_launch(void* const* d_in, const int* in_sizes, int n_in,
                              void* d_out, int out_size) {
    const float* x     = (const float*)d_in[0];
    const float* W_i   = (const float*)d_in[1];
    const float* U_i   = (const float*)d_in[2];
    const float* b_i   = (const float*)d_in[3];
    const float* W_ste = (const float*)d_in[4];
    const float* U_ste = (const float*)d_in[5];
    const float* b_ste = (const float*)d_in[6];
    const float* W_fre = (const float*)d_in[7];
    const float* U_fre = (const float*)d_in[8];
    const float* b_fre = (const float*)d_in[9];
    const float* W_c   = (const float*)d_in[10];
    const float* U_c   = (const float*)d_in[11];
    const float* b_c   = (const float*)d_in[12];
    const float* W_o   = (const float*)d_in[13];
    const float* U_o   = (const float*)d_in[14];
    const float* b_o   = (const float*)d_in[15];
    const float* U_a   = (const float*)d_in[16];
    const float* b_a   = (const float*)d_in[17];
    const float* W_p   = (const float*)d_in[18];
    const float* b_p   = (const float*)d_in[19];

    (void)in_sizes; (void)n_in; (void)out_size;

    prep_kernel<<<(4 * Hh * 32 + 255) / 256, 256>>>(U_i, U_ste, U_c, U_o);
    sfm_kernel<<<Bb / 4, 128>>>(x, W_i, b_i, W_ste, b_ste, W_fre, U_fre, b_fre,
                                W_c, b_c, W_o, b_o, U_a, b_a, W_p, b_p,
                                (float*)d_out);
}

// round 10
// speedup vs baseline: 2.7220x; 2.7220x over previous
#include <cuda_runtime.h>
#include <cuda_bf16.h>
#include <math.h>

#define Hh 64
#define Ff 10
#define Tt 60
#define Dd 6
#define Bb 2048

typedef unsigned long long ull;

// bf16 recurrent weights as natural (gate0,gate1) pairs, per gate-role w:
//   w=0: (G0,G1) = (U_i,U_ste);  w=1: (U_c,U_o)
// g_Ub2[w][j*32+lane] = { bf16x2(G0,G1)@h=lane , bf16x2(G0,G1)@h=lane+32 }
__device__ ull g_Ub2[2][Hh * 32];

__device__ __forceinline__ unsigned int bpack(float a, float b) {
    __nv_bfloat162 p = __floats2bfloat162_rn(a, b);
    return *reinterpret_cast<unsigned int*>(&p);
}

__global__ void prep_kernel(const float* __restrict__ Ui, const float* __restrict__ Us,
                            const float* __restrict__ Uc, const float* __restrict__ Uo) {
    int idx = blockIdx.x * blockDim.x + threadIdx.x;   // [0, 2*64*32)
    if (idx < 2 * Hh * 32) {
        int w = idx >> 11, r = idx & 2047;
        int j = r >> 5, lane = r & 31;
        const float* G0 = w ? Uc : Ui;
        const float* G1 = w ? Uo : Us;
        unsigned int lo = bpack(G0[j * Hh + lane],      G1[j * Hh + lane]);
        unsigned int hi = bpack(G0[j * Hh + lane + 32], G1[j * Hh + lane + 32]);
        g_Ub2[w][r] = ((ull)hi << 32) | (ull)lo;
    }
}

__device__ __forceinline__ float hsig(float v) {
    return __saturatef(fmaf(v, 0.16666667f, 0.5f));
}
__device__ __forceinline__ ull pack2(float lo, float hi) {
    ull r; asm("mov.b64 %0, {%1, %2};" : "=l"(r) : "f"(lo), "f"(hi)); return r;
}
__device__ __forceinline__ ull fma2(ull a, ull b, ull c) {
    ull d; asm("fma.rn.f32x2 %0, %1, %2, %3;" : "=l"(d) : "l"(a), "l"(b), "l"(c)); return d;
}
__device__ __forceinline__ ull add2(ull a, ull b) {
    ull d; asm("add.rn.f32x2 %0, %1, %2;" : "=l"(d) : "l"(a), "l"(b)); return d;
}
__device__ __forceinline__ float2 unpack2(ull v) {
    float lo, hi; asm("mov.b64 {%0, %1}, %2;" : "=f"(lo), "=f"(hi) : "l"(v));
    return make_float2(lo, hi);
}
// bf16x2(G0,G1) -> f32x2 (G0,G1): 2 ALU ops (latency filler between LDS and FFMA2).
__device__ __forceinline__ ull bf2f2(unsigned int u) {
    float lo = __uint_as_float(u << 16);
    float hi = __uint_as_float(u & 0xFFFF0000u);
    return pack2(lo, hi);
}
// tanh(x) = 1 - 2/(exp(2x)+1): MUFU.EX2 + MUFU.RCP, abs err ~1e-6
__device__ __forceinline__ float ftanh(float x) {
    float e = __expf(2.0f * x);
    float r;
    asm("rcp.approx.f32 %0, %1;" : "=f"(r) : "f"(e + 1.0f));
    return fmaf(-2.0f, r, 1.0f);
}

// Block = 64 threads = 2 gate-split warps sharing 4 batches.
// Warp 0 computes gates (i,ste) for all 4 batches; warp 1 computes (c,o).
// Warp w runs the elementwise tail + fre for batches {2w, 2w+1}.
// Lane owns h-columns {lane, lane+32}. U lives in shared (bf16), staged once.
__global__ __launch_bounds__(64) void sfm_kernel(
    const float* __restrict__ x,
    const float* __restrict__ W_i,   const float* __restrict__ b_i,
    const float* __restrict__ W_ste, const float* __restrict__ b_ste,
    const float* __restrict__ W_fre, const float* __restrict__ U_fre, const float* __restrict__ b_fre,
    const float* __restrict__ W_c,   const float* __restrict__ b_c,
    const float* __restrict__ W_o,   const float* __restrict__ b_o,
    const float* __restrict__ U_a,   const float* __restrict__ b_a,
    const float* __restrict__ W_p,   const float* __restrict__ b_p,
    float* __restrict__ out)
{
    __shared__ __align__(16) uint2  sh_Ub[2][Hh][32];  // bf16 U, 32 KB
    __shared__ __align__(16) float4 sh_x4[Tt][Dd];     // (b0,b1,b2,b3)
    __shared__ __align__(16) ull    sh_hd[Hh][4];      // dup (h,h) pairs [col][b]
    __shared__ __align__(16) ull    sh_ex[2][32][4];   // gate exchange [writer][lane][hs*2+bl]
    __shared__ float                sh_UfT[Ff * 65];   // [f][j], padded rows
    __shared__ ull                  sh_mpk[Tt];        // packed nibble idx m(t,f)
    __shared__ __align__(8) float2  sh_tbl[16];        // 10 distinct (cos,sin)

    const int tid  = threadIdx.x;
    const int lane = tid & 31;
    const int w    = tid >> 5;            // 0 = (i,ste) warp, 1 = (c,o) warp
    const int bbase = blockIdx.x * 4;

    // ---- one-time staging ----
    {   // U: 2048 uint4 = 32 KB
        const uint4* gsrc = reinterpret_cast<const uint4*>(&g_Ub2[0][0]);
        uint4* sdst = reinterpret_cast<uint4*>(&sh_Ub[0][0][0]);
        for (int i = tid; i < 2 * Hh * 32 / 2; i += 64) sdst[i] = gsrc[i];
    }
    const float* xg = x + (size_t)bbase * (Tt * Dd);
    for (int i = tid; i < Tt * Dd; i += 64) {
        sh_x4[i / Dd][i % Dd] = make_float4(xg[0 * Tt * Dd + i], xg[1 * Tt * Dd + i],
                                            xg[2 * Tt * Dd + i], xg[3 * Tt * Dd + i]);
    }
    for (int i = tid; i < Ff * Hh; i += 64) {
        int f = i / Hh, j = i % Hh;
        sh_UfT[f * 65 + j] = U_fre[j * Ff + f];
    }
    for (int i = tid; i < Tt; i += 64) {
        ull v = 0;
#pragma unroll
        for (int f = 1; f < Ff; f++)
            v |= (ull)(((i + 1) * f) % Ff) << (4 * f);
        sh_mpk[i] = v;
    }
    if (tid < Ff) {
        float s, c;
        sincosf((float)tid * 0.62831853071795864769f, &s, &c);   // 2*pi/10
        sh_tbl[tid] = make_float2(c, s);
    }
#pragma unroll
    for (int b = 0; b < 4; b++) sh_hd[tid][b] = 0ull;

    // ---- per-lane constants ----
    const int h0 = lane, h1 = lane + 32;
    const float* Wg0 = w ? W_c : W_i;
    const float* Wg1 = w ? W_o : W_ste;
    const float* bg0 = w ? b_c : b_i;
    const float* bg1 = w ? b_o : b_ste;
    ull Wp_[2][Dd];   // W as natural (g0,g1) pairs: [hslot][d]
#pragma unroll
    for (int d = 0; d < Dd; d++) {
        Wp_[0][d] = pack2(Wg0[d * Hh + h0], Wg1[d * Hh + h0]);
        Wp_[1][d] = pack2(Wg0[d * Hh + h1], Wg1[d * Hh + h1]);
    }
    const ull bp_[2] = { pack2(bg0[h0], bg1[h0]), pack2(bg0[h1], bg1[h1]) };
    const float ba_[2] = { b_a[h0], b_a[h1] };
    float ua[Ff];
#pragma unroll
    for (int f = 0; f < Ff; f++) ua[f] = U_a[f];

    // fre duty: lanes 0..19 -> local batch fb = lane/10, freq ff = lane%10.
    const bool duty = (lane < 2 * Ff);
    const int  fb = lane / Ff, ff = lane % Ff;
    float wfre[Dd];
#pragma unroll
    for (int d = 0; d < Dd; d++) wfre[d] = W_fre[d * Ff + ff];
    const float bfre = b_fre[ff];

    // Oscillator state for my 2 tail batches: [bl][hslot][f]
    float sre[2][2][Ff], sim[2][2][Ff];
#pragma unroll
    for (int bl = 0; bl < 2; bl++)
#pragma unroll
        for (int hs = 0; hs < 2; hs++)
#pragma unroll
            for (int f = 0; f < Ff; f++) { sre[bl][hs][f] = 0.0f; sim[bl][hs][f] = 0.0f; }

    float hlast[2][2];   // [bl][hslot], for the epilogue

    __syncthreads();

    for (int t = 0; t < Tt; t++) {
        // ---- seeds: acc[hs][b] = (g0,g1) bias + x_t @ (Wg0,Wg1) ----
        ull acc[2][4];
#pragma unroll
        for (int b = 0; b < 4; b++) { acc[0][b] = bp_[0]; acc[1][b] = bp_[1]; }
        float af = bfre;
#pragma unroll
        for (int d = 0; d < Dd; d++) {
            float4 xv = sh_x4[t][d];             // LDS.128 broadcast
            ull x0 = pack2(xv.x, xv.x);
            ull x1 = pack2(xv.y, xv.y);
            ull x2 = pack2(xv.z, xv.z);
            ull x3 = pack2(xv.w, xv.w);
            acc[0][0] = fma2(x0, Wp_[0][d], acc[0][0]);
            acc[1][0] = fma2(x0, Wp_[1][d], acc[1][0]);
            acc[0][1] = fma2(x1, Wp_[0][d], acc[0][1]);
            acc[1][1] = fma2(x1, Wp_[1][d], acc[1][1]);
            acc[0][2] = fma2(x2, Wp_[0][d], acc[0][2]);
            acc[1][2] = fma2(x2, Wp_[1][d], acc[1][2]);
            acc[0][3] = fma2(x3, Wp_[0][d], acc[0][3]);
            acc[1][3] = fma2(x3, Wp_[1][d], acc[1][3]);
            float xd = fb ? (w ? xv.w : xv.y) : (w ? xv.z : xv.x);
            af = fmaf(xd, wfre[d], af);
        }

        // ---- recurrent matmul: bf16 U from shared (LDS.64) x dup-h; cvt as filler ----
#pragma unroll 8
        for (int j = 0; j < Hh; j++) {
            uint2 uu = sh_Ub[w][j][lane];                       // LDS.64, conflict-free
            ulonglong2 hA = *(const ulonglong2*)&sh_hd[j][0];   // (b0b0,b1b1) bcast
            ulonglong2 hB = *(const ulonglong2*)&sh_hd[j][2];   // (b2b2,b3b3)
            ull u0 = bf2f2(uu.x);                               // (g0,g1) @ h0
            ull u1 = bf2f2(uu.y);                               // (g0,g1) @ h1
            acc[0][0] = fma2(hA.x, u0, acc[0][0]);
            acc[1][0] = fma2(hA.x, u1, acc[1][0]);
            acc[0][1] = fma2(hA.y, u0, acc[0][1]);
            acc[1][1] = fma2(hA.y, u1, acc[1][1]);
            acc[0][2] = fma2(hB.x, u0, acc[0][2]);
            acc[1][2] = fma2(hB.x, u1, acc[1][2]);
            acc[0][3] = fma2(hB.y, u0, acc[0][3]);
            acc[1][3] = fma2(hB.y, u1, acc[1][3]);
            if (duty) {
                ull hown = w ? (fb ? hB.y : hB.x) : (fb ? hA.y : hA.x);
                af = fmaf(unpack2(hown).x, sh_UfT[ff * 65 + j], af);
            }
        }
        const float frev = hsig(af);   // valid on duty lanes

        // ---- exchange: send my gate pairs for the PEER's 2 batches ----
        {
            int pb = 2 * (1 - w);
            ulonglong2* dst = reinterpret_cast<ulonglong2*>(&sh_ex[w][lane][0]);
            dst[0] = make_ulonglong2(acc[0][pb],     acc[1][pb]);
            dst[1] = make_ulonglong2(acc[0][pb + 1], acc[1][pb + 1]);
        }
        __syncthreads();   // exchange visible; sh_hd reads of this step done
        ull peer[2][2];    // [bl][hs]
        {
            const ulonglong2* src = reinterpret_cast<const ulonglong2*>(&sh_ex[1 - w][lane][0]);
            ulonglong2 s0 = src[0], s1 = src[1];
            peer[0][0] = s0.x; peer[0][1] = s0.y;
            peer[1][0] = s1.x; peer[1][1] = s1.y;
        }

        // ---- elementwise tail for my 2 batches ----
        float cs[Ff], sn[Ff];
        {
            ull mp = sh_mpk[t];
#pragma unroll
            for (int f = 0; f < Ff; f++) {
                float2 cn = sh_tbl[(int)((mp >> (4 * f)) & 15)];  // uniform bcast
                cs[f] = cn.x; sn[f] = cn.y;
            }
        }
#pragma unroll
        for (int bl = 0; bl < 2; bl++) {
            float fre_b[Ff];
#pragma unroll
            for (int f = 0; f < Ff; f++)
                fre_b[f] = __shfl_sync(0xffffffffu, frev, bl * Ff + f);
            int b = 2 * w + bl;
#pragma unroll
            for (int hs = 0; hs < 2; hs++) {
                float2 mine = unpack2(acc[hs][b]);
                float2 thrs = unpack2(peer[bl][hs]);
                float pi   = w ? thrs.x : mine.x;
                float pste = w ? thrs.y : mine.y;
                float pc   = w ? mine.x : thrs.x;
                float po   = w ? mine.y : thrs.y;
                float iv = hsig(pi);
                float sv = hsig(pste);
                float ov = hsig(po);
                float cv = iv * ftanh(pc);
                float acca = ba_[hs];
#pragma unroll
                for (int f = 0; f < Ff; f++) {
                    float fv = sv * fre_b[f];
                    float r = fmaf(fv, sre[bl][hs][f], cv * cs[f]);
                    float m = fmaf(fv, sim[bl][hs][f], cv * sn[f]);
                    sre[bl][hs][f] = r;
                    sim[bl][hs][f] = m;
                    acca = fmaf(fmaf(r, r, m * m), ua[f], acca);
                }
                hlast[bl][hs] = ov * ftanh(acca);
            }
        }
        // Publish my 2 batches' h as dup pairs at both columns.
        {
            ulonglong2* r0 = reinterpret_cast<ulonglong2*>(&sh_hd[h0][2 * w]);
            ulonglong2* r1 = reinterpret_cast<ulonglong2*>(&sh_hd[h1][2 * w]);
            *r0 = make_ulonglong2(pack2(hlast[0][0], hlast[0][0]),
                                  pack2(hlast[1][0], hlast[1][0]));
            *r1 = make_ulonglong2(pack2(hlast[0][1], hlast[0][1]),
                                  pack2(hlast[1][1], hlast[1][1]));
        }
        __syncthreads();   // new h visible for next step
    }

    // ---- projection: out[b] = h @ W_p + b_p (warp butterfly over my 2 batches) ----
    {
        float wp0 = W_p[h0], wp1 = W_p[h1];
        float p0 = fmaf(hlast[0][0], wp0, hlast[0][1] * wp1);
        float p1 = fmaf(hlast[1][0], wp0, hlast[1][1] * wp1);
        ull pp = pack2(p0, p1);
#pragma unroll
        for (int off = 16; off >= 1; off >>= 1)
            pp = add2(pp, __shfl_xor_sync(0xffffffffu, pp, off));
        if (lane == 0) {
            float2 r = unpack2(pp);
            float bpv = b_p[0];
            out[bbase + 2 * w]     = r.x + bpv;
            out[bbase + 2 * w + 1] = r.y + bpv;
        }
    }
}

extern "C" void kernel_launch(void* const* d_in, const int* in_sizes, int n_in,
                              void* d_out, int out_size) {
    const float* x     = (const float*)d_in[0];
    const float* W_i   = (const float*)d_in[1];
    const float* U_i   = (const float*)d_in[2];
    const float* b_i   = (const float*)d_in[3];
    const float* W_ste = (const float*)d_in[4];
    const float* U_ste = (const float*)d_in[5];
    const float* b_ste = (const float*)d_in[6];
    const float* W_fre = (const float*)d_in[7];
    const float* U_fre = (const float*)d_in[8];
    const float* b_fre = (const float*)d_in[9];
    const float* W_c   = (const float*)d_in[10];
    const float* U_c   = (const float*)d_in[11];
    const float* b_c   = (const float*)d_in[12];
    const float* W_o   = (const float*)d_in[13];
    const float* U_o   = (const float*)d_in[14];
    const float* b_o   = (const float*)d_in[15];
    const float* U_a   = (const float*)d_in[16];
    const float* b_a   = (const float*)d_in[17];
    const float* W_p   = (const float*)d_in[18];
    const float* b_p   = (const float*)d_in[19];

    (void)in_sizes; (void)n_in; (void)out_size;

    prep_kernel<<<(2 * Hh * 32 + 255) / 256, 256>>>(U_i, U_ste, U_c, U_o);
    sfm_kernel<<<Bb / 4, 64>>>(x, W_i, b_i, W_ste, b_ste, W_fre, U_fre, b_fre,
                               W_c, b_c, W_o, b_o, U_a, b_a, W_p, b_p,
                               (float*)d_out);
}